// round 1
// baseline (speedup 1.0000x reference)
#include <cuda_runtime.h>
#include <cstdint>

// ---------------------------------------------------------------------------
// SpatialPolicyHead: B=256, S=128 (use rows 3..66 + row 0), H=1024, D=256, V=1858
//   fp = sq_hidden @ Wf^T + bf          (B*64, 256)
//   tp = sq_hidden @ Wt^T + bt          (B*64, 256)
//   gp = hidden[:,0,:] @ Wg^T + bg      (B, 256)
//   out[b,v] = sum_d relu(fp[b,f(v),d]*tp[b,t(v),d] + gp[b,d] + promo[p(v),d]) * Ws[d] + bs
// ---------------------------------------------------------------------------

#define BM 128
#define BN 128
#define BK 16

// scratch (static device globals -- allocation-free)
__device__ float g_fpt[16384 * 512];   // [B*64][512]: cols 0..255 = fp, 256..511 = tp
__device__ float g_gp [256 * 256];     // [B][256]

// ---------------------------------------------------------------------------
// Fused fp/tp GEMM: C[m][n], m in [0,16384) -> (b = m/64, s = m%64, hidden row b*128+3+s)
// n in [0,512): n<256 -> Wf row n, else Wt row n-256. K = 1024.
// 128x128 tile, 256 threads, 8x8 micro-tile, double-buffered smem.
// ---------------------------------------------------------------------------
__global__ void __launch_bounds__(256, 2) gemm_fpt_kernel(
    const float* __restrict__ hidden,
    const float* __restrict__ Wf, const float* __restrict__ Wt,
    const float* __restrict__ bf, const float* __restrict__ bt)
{
    __shared__ float As[2][BK][BM];
    __shared__ float Bs[2][BK][BN];

    const int tid = threadIdx.x;
    const int bm  = blockIdx.y;   // 0..127
    const int bn  = blockIdx.x;   // 0..3

    // global-load assignment: each thread loads 8 consecutive k for one row
    const int g_row = tid >> 1;          // 0..127
    const int g_k   = (tid & 1) * 8;     // 0 or 8

    const int m_g   = bm * BM + g_row;
    const int batch = m_g >> 6;
    const int srow  = m_g & 63;
    const float* Ag = hidden + (size_t)(batch * 128 + 3 + srow) * 1024 + g_k;

    const int n_g   = bn * BN + g_row;
    const float* Bg = ((n_g < 256) ? (Wf + (size_t)n_g * 1024)
                                   : (Wt + (size_t)(n_g - 256) * 1024)) + g_k;

    const int tx = tid & 15;   // n direction
    const int ty = tid >> 4;   // m direction

    float acc[8][8];
    #pragma unroll
    for (int i = 0; i < 8; i++)
        #pragma unroll
        for (int j = 0; j < 8; j++) acc[i][j] = 0.f;

    // preload tile 0
    float4 a0 = ((const float4*)Ag)[0];
    float4 a1 = ((const float4*)Ag)[1];
    float4 b0 = ((const float4*)Bg)[0];
    float4 b1 = ((const float4*)Bg)[1];

    int buf = 0;
    #pragma unroll
    for (int j = 0; j < 4; j++) {
        As[0][g_k + j    ][g_row] = ((float*)&a0)[j];
        As[0][g_k + 4 + j][g_row] = ((float*)&a1)[j];
        Bs[0][g_k + j    ][g_row] = ((float*)&b0)[j];
        Bs[0][g_k + 4 + j][g_row] = ((float*)&b1)[j];
    }
    __syncthreads();

    const int KT = 1024 / BK;   // 64 k-tiles
    for (int t = 0; t < KT; t++) {
        if (t + 1 < KT) {
            const float4* Ag4 = (const float4*)(Ag + (t + 1) * BK);
            const float4* Bg4 = (const float4*)(Bg + (t + 1) * BK);
            a0 = Ag4[0]; a1 = Ag4[1];
            b0 = Bg4[0]; b1 = Bg4[1];
        }
        #pragma unroll
        for (int kk = 0; kk < BK; kk++) {
            float af[8], bv[8];
            *(float4*)&af[0] = *(const float4*)&As[buf][kk][ty * 4];
            *(float4*)&af[4] = *(const float4*)&As[buf][kk][64 + ty * 4];
            *(float4*)&bv[0] = *(const float4*)&Bs[buf][kk][tx * 4];
            *(float4*)&bv[4] = *(const float4*)&Bs[buf][kk][64 + tx * 4];
            #pragma unroll
            for (int i = 0; i < 8; i++)
                #pragma unroll
                for (int j = 0; j < 8; j++)
                    acc[i][j] = fmaf(af[i], bv[j], acc[i][j]);
        }
        if (t + 1 < KT) {
            buf ^= 1;
            #pragma unroll
            for (int j = 0; j < 4; j++) {
                As[buf][g_k + j    ][g_row] = ((float*)&a0)[j];
                As[buf][g_k + 4 + j][g_row] = ((float*)&a1)[j];
                Bs[buf][g_k + j    ][g_row] = ((float*)&b0)[j];
                Bs[buf][g_k + 4 + j][g_row] = ((float*)&b1)[j];
            }
            __syncthreads();
        }
    }

    // epilogue: add bias, write to g_fpt
    const size_t Cbase = (size_t)(bm * BM) * 512 + (size_t)(bn * BN);
    #pragma unroll
    for (int i = 0; i < 8; i++) {
        const int mi = (i < 4) ? (ty * 4 + i) : (64 + ty * 4 + (i - 4));
        #pragma unroll
        for (int jg = 0; jg < 2; jg++) {
            const int nofs   = jg * 64 + tx * 4;
            const int n_glob = bn * BN + nofs;
            const float* bias = (n_glob < 256) ? (bf + n_glob) : (bt + (n_glob - 256));
            float4 r;
            r.x = acc[i][jg * 4 + 0] + bias[0];
            r.y = acc[i][jg * 4 + 1] + bias[1];
            r.z = acc[i][jg * 4 + 2] + bias[2];
            r.w = acc[i][jg * 4 + 3] + bias[3];
            *(float4*)&g_fpt[Cbase + (size_t)mi * 512 + nofs] = r;
        }
    }
}

// ---------------------------------------------------------------------------
// gp GEMM: 64 blocks x 4 batches; each thread owns one n for 4 batches.
// hidden rows are smem-broadcast; Wg rows streamed per thread (L1/L2 resident).
// ---------------------------------------------------------------------------
__global__ void __launch_bounds__(256) gp_kernel(
    const float* __restrict__ hidden,
    const float* __restrict__ Wg, const float* __restrict__ bg)
{
    __shared__ float sh[4][1024];
    const int tid = threadIdx.x;
    const int b0  = blockIdx.x * 4;

    // load 4 global-hidden rows: 4096 floats = 1024 float4 / 256 threads
    #pragma unroll
    for (int i = 0; i < 4; i++) {
        const int idx = tid + i * 256;   // float4 index
        const int row = idx >> 8;
        const int col = idx & 255;
        ((float4*)&sh[row][0])[col] =
            ((const float4*)(hidden + (size_t)(b0 + row) * 131072))[col];
    }
    __syncthreads();

    const int n = tid;
    const float4* w4 = (const float4*)(Wg + (size_t)n * 1024);
    float acc0 = 0.f, acc1 = 0.f, acc2 = 0.f, acc3 = 0.f;
    #pragma unroll 4
    for (int k4 = 0; k4 < 256; k4++) {
        const float4 w  = w4[k4];
        const float4 h0 = ((const float4*)&sh[0][0])[k4];
        const float4 h1 = ((const float4*)&sh[1][0])[k4];
        const float4 h2 = ((const float4*)&sh[2][0])[k4];
        const float4 h3 = ((const float4*)&sh[3][0])[k4];
        acc0 = fmaf(w.x, h0.x, acc0); acc0 = fmaf(w.y, h0.y, acc0);
        acc0 = fmaf(w.z, h0.z, acc0); acc0 = fmaf(w.w, h0.w, acc0);
        acc1 = fmaf(w.x, h1.x, acc1); acc1 = fmaf(w.y, h1.y, acc1);
        acc1 = fmaf(w.z, h1.z, acc1); acc1 = fmaf(w.w, h1.w, acc1);
        acc2 = fmaf(w.x, h2.x, acc2); acc2 = fmaf(w.y, h2.y, acc2);
        acc2 = fmaf(w.z, h2.z, acc2); acc2 = fmaf(w.w, h2.w, acc2);
        acc3 = fmaf(w.x, h3.x, acc3); acc3 = fmaf(w.y, h3.y, acc3);
        acc3 = fmaf(w.z, h3.z, acc3); acc3 = fmaf(w.w, h3.w, acc3);
    }
    const float bias = bg[n];
    g_gp[(size_t)(b0 + 0) * 256 + n] = acc0 + bias;
    g_gp[(size_t)(b0 + 1) * 256 + n] = acc1 + bias;
    g_gp[(size_t)(b0 + 2) * 256 + n] = acc2 + bias;
    g_gp[(size_t)(b0 + 3) * 256 + n] = acc3 + bias;
}

// ---------------------------------------------------------------------------
// Combine: one block per batch. SMEM holds the batch's fp/tp (64x512),
// gp row, Ws, promo_tab. One warp per v; float4 LDS; shfl reduce.
// dynamic smem = (32768 + 256 + 256 + 1280) * 4 = 138240 B
// ---------------------------------------------------------------------------
__global__ void __launch_bounds__(512) combine_kernel(
    const float* __restrict__ promo_tab, const float* __restrict__ Ws,
    const float* __restrict__ bs,
    const int* __restrict__ from_sqs, const int* __restrict__ to_sqs,
    const int* __restrict__ promo_types,
    float* __restrict__ out)
{
    extern __shared__ float smem[];
    float* fpt_s   = smem;             // 64*512
    float* gp_s    = smem + 32768;     // 256
    float* ws_s    = gp_s + 256;       // 256
    float* promo_s = ws_s + 256;       // 5*256

    const int tid = threadIdx.x;
    const int b   = blockIdx.x;

    // stage this batch's fp/tp rows: 32768 floats = 8192 float4 / 512 threads
    const float4* src = (const float4*)(g_fpt + (size_t)b * 32768);
    float4* dst = (float4*)fpt_s;
    #pragma unroll
    for (int i = 0; i < 16; i++)
        dst[tid + i * 512] = src[tid + i * 512];
    if (tid < 256) {
        gp_s[tid] = g_gp[(size_t)b * 256 + tid];
        ws_s[tid] = Ws[tid];
    }
    if (tid < 320)
        ((float4*)promo_s)[tid] = ((const float4*)promo_tab)[tid];
    __syncthreads();

    const int warp = tid >> 5;
    const int lane = tid & 31;
    const float bs0 = bs[0];

    for (int v = warp; v < 1858; v += 16) {
        const int f = from_sqs[v];
        const int t = to_sqs[v];
        const int p = promo_types[v];
        const float* fr = fpt_s + f * 512;          // fp cols 0..255
        const float* tr = fpt_s + t * 512 + 256;    // tp cols 256..511
        const float* pr = promo_s + p * 256;
        float acc = 0.f;
        #pragma unroll
        for (int h = 0; h < 2; h++) {
            const int d = h * 128 + lane * 4;
            const float4 a  = *(const float4*)(fr + d);
            const float4 bb = *(const float4*)(tr + d);
            const float4 g  = *(const float4*)(gp_s + d);
            const float4 pm = *(const float4*)(pr + d);
            const float4 w  = *(const float4*)(ws_s + d);
            const float c0 = fmaf(a.x, bb.x, g.x) + pm.x;
            const float c1 = fmaf(a.y, bb.y, g.y) + pm.y;
            const float c2 = fmaf(a.z, bb.z, g.z) + pm.z;
            const float c3 = fmaf(a.w, bb.w, g.w) + pm.w;
            acc = fmaf(fmaxf(c0, 0.f), w.x, acc);
            acc = fmaf(fmaxf(c1, 0.f), w.y, acc);
            acc = fmaf(fmaxf(c2, 0.f), w.z, acc);
            acc = fmaf(fmaxf(c3, 0.f), w.w, acc);
        }
        #pragma unroll
        for (int off = 16; off > 0; off >>= 1)
            acc += __shfl_xor_sync(0xffffffffu, acc, off);
        if (lane == 0)
            out[(size_t)b * 1858 + v] = acc + bs0;
    }
}

// ---------------------------------------------------------------------------
extern "C" void kernel_launch(void* const* d_in, const int* in_sizes, int n_in,
                              void* d_out, int out_size)
{
    (void)in_sizes; (void)n_in; (void)out_size;

    const float* hidden      = (const float*)d_in[0];
    const float* Wf          = (const float*)d_in[1];
    const float* bf          = (const float*)d_in[2];
    const float* Wt          = (const float*)d_in[3];
    const float* bt          = (const float*)d_in[4];
    const float* Wg          = (const float*)d_in[5];
    const float* bg          = (const float*)d_in[6];
    const float* promo_tab   = (const float*)d_in[7];
    const float* Ws          = (const float*)d_in[8];
    const float* bs          = (const float*)d_in[9];
    const int*   from_sqs    = (const int*)d_in[10];
    const int*   to_sqs      = (const int*)d_in[11];
    const int*   promo_types = (const int*)d_in[12];
    float*       out         = (float*)d_out;

    // fp/tp fused GEMM: grid (N tiles = 4, M tiles = 128)
    gemm_fpt_kernel<<<dim3(4, 128), 256>>>(hidden, Wf, Wt, bf, bt);

    // gp: 64 blocks x 4 batches
    gp_kernel<<<64, 256>>>(hidden, Wg, bg);

    // combine: one block per batch, 138240 B dynamic smem
    const int smem_bytes = (32768 + 256 + 256 + 1280) * 4;
    cudaFuncSetAttribute(combine_kernel,
                         cudaFuncAttributeMaxDynamicSharedMemorySize, smem_bytes);
    combine_kernel<<<256, 512, smem_bytes>>>(promo_tab, Ws, bs,
                                             from_sqs, to_sqs, promo_types, out);
}

// round 2
// speedup vs baseline: 1.8143x; 1.8143x over previous
#include <cuda_runtime.h>
#include <cstdint>

// ---------------------------------------------------------------------------
// SpatialPolicyHead: B=256, S=128 (rows 3..66 + row 0), H=1024, D=256, V=1858
//   fp = sq_hidden @ Wf^T + bf          (B*64, 256)
//   tp = sq_hidden @ Wt^T + bt          (B*64, 256)
//   gp = hidden[:,0,:] @ Wg^T + bg      (B, 256)
//   out[b,v] = sum_d relu(fp[b,f(v),d]*tp[b,t(v),d] + gp[b,d] + promo[p(v),d])*Ws[d] + bs
//
// R2: fp/tp GEMM on tensor cores via TF32 mma.sync.m16n8k8 (rna-rounded
// operands prepared by a conversion pre-pass so the GEMM can use cp.async).
// ---------------------------------------------------------------------------

// scratch (static device globals -- allocation-free)
__device__ float g_Aconv[16384 * 1024];  // densified sq_hidden rows, tf32-rounded
__device__ float g_Bconv[512 * 1024];    // Wf (rows 0..255) ++ Wt (rows 256..511), tf32-rounded
__device__ float g_fpt[16384 * 512];     // [B*64][512]: cols 0..255 = fp, 256..511 = tp
__device__ float g_gp [256 * 256];       // [B][256]

__device__ __forceinline__ float tf32r(float x) {
    uint32_t u;
    asm("cvt.rna.tf32.f32 %0, %1;" : "=r"(u) : "f"(x));
    return __uint_as_float(u);
}

// ---------------------------------------------------------------------------
// Conversion pre-pass: gather + tf32-round A and B into dense scratch.
// Blocks [0,4096): A (16384x1024). Blocks [4096,4224): B (512x1024).
// Each thread: 4 float4.
// ---------------------------------------------------------------------------
__global__ void __launch_bounds__(256) conv_kernel(
    const float* __restrict__ hidden,
    const float* __restrict__ Wf, const float* __restrict__ Wt)
{
    const int tid = threadIdx.x;
    if (blockIdx.x < 4096) {
        const size_t base = (size_t)blockIdx.x * 1024;
        #pragma unroll
        for (int j = 0; j < 4; j++) {
            const size_t i = base + tid + j * 256;   // float4 index into g_Aconv
            const int m  = (int)(i >> 8);
            const int c4 = (int)(i & 255);
            const int row = (m >> 6) * 128 + 3 + (m & 63);
            float4 v = ((const float4*)(hidden + (size_t)row * 1024))[c4];
            v.x = tf32r(v.x); v.y = tf32r(v.y); v.z = tf32r(v.z); v.w = tf32r(v.w);
            ((float4*)g_Aconv)[i] = v;
        }
    } else {
        const size_t base = (size_t)(blockIdx.x - 4096) * 1024;
        #pragma unroll
        for (int j = 0; j < 4; j++) {
            const size_t i = base + tid + j * 256;   // float4 index into g_Bconv
            const int n  = (int)(i >> 8);
            const int c4 = (int)(i & 255);
            const float* src = (n < 256) ? (Wf + (size_t)n * 1024)
                                         : (Wt + (size_t)(n - 256) * 1024);
            float4 v = ((const float4*)src)[c4];
            v.x = tf32r(v.x); v.y = tf32r(v.y); v.z = tf32r(v.z); v.w = tf32r(v.w);
            ((float4*)g_Bconv)[i] = v;
        }
    }
}

// ---------------------------------------------------------------------------
// TF32 tensor-core GEMM: C(16384 x 512) = A(16384x1024) @ B(512x1024)^T + bias
// 128x128x32 block tile, 256 threads = 8 warps in 2(m) x 4(n), warp tile 64x32.
// mma.sync.aligned.m16n8k8.row.col.f32.tf32.tf32.f32, cp.async double buffer.
// smem: A[2][128][36] + B[2][128][36] floats = 73728 B (dynamic).
// ---------------------------------------------------------------------------
#define KT 32                 // 1024 / 32 k-tiles
#define BUFSZ (128 * 36)      // floats per buffer per matrix

__device__ __forceinline__ void mma_tf32(float* c, const uint32_t* a, const uint32_t* b) {
    asm volatile(
        "mma.sync.aligned.m16n8k8.row.col.f32.tf32.tf32.f32 "
        "{%0,%1,%2,%3}, {%4,%5,%6,%7}, {%8,%9}, {%0,%1,%2,%3};"
        : "+f"(c[0]), "+f"(c[1]), "+f"(c[2]), "+f"(c[3])
        : "r"(a[0]), "r"(a[1]), "r"(a[2]), "r"(a[3]), "r"(b[0]), "r"(b[1]));
}

__global__ void __launch_bounds__(256, 2) gemm_fpt_kernel(
    const float* __restrict__ bf, const float* __restrict__ bt)
{
    extern __shared__ float smem[];
    float* As = smem;                 // [2][128][36]
    float* Bs = smem + 2 * BUFSZ;     // [2][128][36]
    const uint32_t sbase = (uint32_t)__cvta_generic_to_shared(smem);
    const uint32_t sA_u  = sbase;
    const uint32_t sB_u  = sbase + 2 * BUFSZ * 4;

    const int tid  = threadIdx.x;
    const int bn   = blockIdx.x;    // 0..3
    const int bm   = blockIdx.y;    // 0..127
    const int warp = tid >> 5;
    const int lane = tid & 31;
    const int warp_m = warp >> 2;   // 0..1
    const int warp_n = warp & 3;    // 0..3
    const int lr = lane >> 2;       // 0..7
    const int lc = lane & 3;        // 0..3

    // copy mapping: thread handles rows (tid>>3)+32j, float4 col tid&7
    const int crow = tid >> 3;      // 0..31
    const int cc4  = tid & 7;       // 0..7

    const float* gA = g_Aconv + (size_t)(bm * 128 + crow) * 1024 + cc4 * 4;
    const float* gB = g_Bconv + (size_t)(bn * 128 + crow) * 1024 + cc4 * 4;
    const uint32_t sAoff = (crow * 36 + cc4 * 4) * 4;   // bytes
    const uint32_t sBoff = sAoff;

    float acc[4][4][4];
    #pragma unroll
    for (int i = 0; i < 4; i++)
        #pragma unroll
        for (int j = 0; j < 4; j++)
            #pragma unroll
            for (int k = 0; k < 4; k++) acc[i][j][k] = 0.f;

    // prologue: issue tile 0 into buffer 0
    #pragma unroll
    for (int j = 0; j < 4; j++) {
        asm volatile("cp.async.ca.shared.global [%0], [%1], 16;" ::
            "r"(sA_u + sAoff + j * (32 * 36 * 4)), "l"(gA + (size_t)j * 32 * 1024));
        asm volatile("cp.async.ca.shared.global [%0], [%1], 16;" ::
            "r"(sB_u + sBoff + j * (32 * 36 * 4)), "l"(gB + (size_t)j * 32 * 1024));
    }
    asm volatile("cp.async.commit_group;" ::: "memory");

    int buf = 0;
    for (int t = 0; t < KT; t++) {
        asm volatile("cp.async.wait_group 0;" ::: "memory");
        __syncthreads();

        if (t + 1 < KT) {
            const int nb = buf ^ 1;
            const uint32_t aoff = sA_u + (uint32_t)nb * BUFSZ * 4 + sAoff;
            const uint32_t boff = sB_u + (uint32_t)nb * BUFSZ * 4 + sBoff;
            const float* gAt = gA + (t + 1) * 32;
            const float* gBt = gB + (t + 1) * 32;
            #pragma unroll
            for (int j = 0; j < 4; j++) {
                asm volatile("cp.async.ca.shared.global [%0], [%1], 16;" ::
                    "r"(aoff + j * (32 * 36 * 4)), "l"(gAt + (size_t)j * 32 * 1024));
                asm volatile("cp.async.ca.shared.global [%0], [%1], 16;" ::
                    "r"(boff + j * (32 * 36 * 4)), "l"(gBt + (size_t)j * 32 * 1024));
            }
            asm volatile("cp.async.commit_group;" ::: "memory");
        }

        const float* Ab = As + buf * BUFSZ;
        const float* Bb = Bs + buf * BUFSZ;
        #pragma unroll
        for (int ks = 0; ks < 4; ks++) {
            uint32_t afr[4][4], bfr[4][2];
            #pragma unroll
            for (int mt = 0; mt < 4; mt++) {
                const float* p = Ab + (warp_m * 64 + mt * 16 + lr) * 36 + ks * 8 + lc;
                afr[mt][0] = __float_as_uint(p[0]);
                afr[mt][1] = __float_as_uint(p[8 * 36]);
                afr[mt][2] = __float_as_uint(p[4]);
                afr[mt][3] = __float_as_uint(p[8 * 36 + 4]);
            }
            #pragma unroll
            for (int nt = 0; nt < 4; nt++) {
                const float* q = Bb + (warp_n * 32 + nt * 8 + lr) * 36 + ks * 8 + lc;
                bfr[nt][0] = __float_as_uint(q[0]);
                bfr[nt][1] = __float_as_uint(q[4]);
            }
            #pragma unroll
            for (int mt = 0; mt < 4; mt++)
                #pragma unroll
                for (int nt = 0; nt < 4; nt++)
                    mma_tf32(acc[mt][nt], afr[mt], bfr[nt]);
        }
        buf ^= 1;
    }

    // epilogue: add bias, store float2 pairs
    #pragma unroll
    for (int mt = 0; mt < 4; mt++) {
        const int gm0 = bm * 128 + warp_m * 64 + mt * 16 + lr;
        #pragma unroll
        for (int nt = 0; nt < 4; nt++) {
            const int gn = bn * 128 + warp_n * 32 + nt * 8 + (lc << 1);
            const float* bia = (gn < 256) ? (bf + gn) : (bt + gn - 256);
            const float b0 = bia[0], b1 = bia[1];
            float2 r0, r1;
            r0.x = acc[mt][nt][0] + b0; r0.y = acc[mt][nt][1] + b1;
            r1.x = acc[mt][nt][2] + b0; r1.y = acc[mt][nt][3] + b1;
            *(float2*)&g_fpt[(size_t)gm0 * 512 + gn]       = r0;
            *(float2*)&g_fpt[(size_t)(gm0 + 8) * 512 + gn] = r1;
        }
    }
}

// ---------------------------------------------------------------------------
// gp GEMM (fp32, tiny): 64 blocks x 4 batches.
// ---------------------------------------------------------------------------
__global__ void __launch_bounds__(256) gp_kernel(
    const float* __restrict__ hidden,
    const float* __restrict__ Wg, const float* __restrict__ bg)
{
    __shared__ float sh[4][1024];
    const int tid = threadIdx.x;
    const int b0  = blockIdx.x * 4;

    #pragma unroll
    for (int i = 0; i < 4; i++) {
        const int idx = tid + i * 256;
        const int row = idx >> 8;
        const int col = idx & 255;
        ((float4*)&sh[row][0])[col] =
            ((const float4*)(hidden + (size_t)(b0 + row) * 131072))[col];
    }
    __syncthreads();

    const int n = tid;
    const float4* w4 = (const float4*)(Wg + (size_t)n * 1024);
    float acc0 = 0.f, acc1 = 0.f, acc2 = 0.f, acc3 = 0.f;
    #pragma unroll 4
    for (int k4 = 0; k4 < 256; k4++) {
        const float4 w  = w4[k4];
        const float4 h0 = ((const float4*)&sh[0][0])[k4];
        const float4 h1 = ((const float4*)&sh[1][0])[k4];
        const float4 h2 = ((const float4*)&sh[2][0])[k4];
        const float4 h3 = ((const float4*)&sh[3][0])[k4];
        acc0 = fmaf(w.x, h0.x, acc0); acc0 = fmaf(w.y, h0.y, acc0);
        acc0 = fmaf(w.z, h0.z, acc0); acc0 = fmaf(w.w, h0.w, acc0);
        acc1 = fmaf(w.x, h1.x, acc1); acc1 = fmaf(w.y, h1.y, acc1);
        acc1 = fmaf(w.z, h1.z, acc1); acc1 = fmaf(w.w, h1.w, acc1);
        acc2 = fmaf(w.x, h2.x, acc2); acc2 = fmaf(w.y, h2.y, acc2);
        acc2 = fmaf(w.z, h2.z, acc2); acc2 = fmaf(w.w, h2.w, acc2);
        acc3 = fmaf(w.x, h3.x, acc3); acc3 = fmaf(w.y, h3.y, acc3);
        acc3 = fmaf(w.z, h3.z, acc3); acc3 = fmaf(w.w, h3.w, acc3);
    }
    const float bias = bg[n];
    g_gp[(size_t)(b0 + 0) * 256 + n] = acc0 + bias;
    g_gp[(size_t)(b0 + 1) * 256 + n] = acc1 + bias;
    g_gp[(size_t)(b0 + 2) * 256 + n] = acc2 + bias;
    g_gp[(size_t)(b0 + 3) * 256 + n] = acc3 + bias;
}

// ---------------------------------------------------------------------------
// Combine: one block per batch; 1 warp per v; shfl reduce.
// ---------------------------------------------------------------------------
__global__ void __launch_bounds__(512) combine_kernel(
    const float* __restrict__ promo_tab, const float* __restrict__ Ws,
    const float* __restrict__ bs,
    const int* __restrict__ from_sqs, const int* __restrict__ to_sqs,
    const int* __restrict__ promo_types,
    float* __restrict__ out)
{
    extern __shared__ float smem[];
    float* fpt_s   = smem;             // 64*512
    float* gp_s    = smem + 32768;     // 256
    float* ws_s    = gp_s + 256;       // 256
    float* promo_s = ws_s + 256;       // 5*256

    const int tid = threadIdx.x;
    const int b   = blockIdx.x;

    const float4* src = (const float4*)(g_fpt + (size_t)b * 32768);
    float4* dst = (float4*)fpt_s;
    #pragma unroll
    for (int i = 0; i < 16; i++)
        dst[tid + i * 512] = src[tid + i * 512];
    if (tid < 256) {
        gp_s[tid] = g_gp[(size_t)b * 256 + tid];
        ws_s[tid] = Ws[tid];
    }
    if (tid < 320)
        ((float4*)promo_s)[tid] = ((const float4*)promo_tab)[tid];
    __syncthreads();

    const int warp = tid >> 5;
    const int lane = tid & 31;
    const float bs0 = bs[0];

    for (int v = warp; v < 1858; v += 16) {
        const int f = from_sqs[v];
        const int t = to_sqs[v];
        const int p = promo_types[v];
        const float* fr = fpt_s + f * 512;
        const float* tr = fpt_s + t * 512 + 256;
        const float* pr = promo_s + p * 256;
        float acc = 0.f;
        #pragma unroll
        for (int h = 0; h < 2; h++) {
            const int d = h * 128 + lane * 4;
            const float4 a  = *(const float4*)(fr + d);
            const float4 bb = *(const float4*)(tr + d);
            const float4 g  = *(const float4*)(gp_s + d);
            const float4 pm = *(const float4*)(pr + d);
            const float4 w  = *(const float4*)(ws_s + d);
            const float c0 = fmaf(a.x, bb.x, g.x) + pm.x;
            const float c1 = fmaf(a.y, bb.y, g.y) + pm.y;
            const float c2 = fmaf(a.z, bb.z, g.z) + pm.z;
            const float c3 = fmaf(a.w, bb.w, g.w) + pm.w;
            acc = fmaf(fmaxf(c0, 0.f), w.x, acc);
            acc = fmaf(fmaxf(c1, 0.f), w.y, acc);
            acc = fmaf(fmaxf(c2, 0.f), w.z, acc);
            acc = fmaf(fmaxf(c3, 0.f), w.w, acc);
        }
        #pragma unroll
        for (int off = 16; off > 0; off >>= 1)
            acc += __shfl_xor_sync(0xffffffffu, acc, off);
        if (lane == 0)
            out[(size_t)b * 1858 + v] = acc + bs0;
    }
}

// ---------------------------------------------------------------------------
extern "C" void kernel_launch(void* const* d_in, const int* in_sizes, int n_in,
                              void* d_out, int out_size)
{
    (void)in_sizes; (void)n_in; (void)out_size;

    const float* hidden      = (const float*)d_in[0];
    const float* Wf          = (const float*)d_in[1];
    const float* bf          = (const float*)d_in[2];
    const float* Wt          = (const float*)d_in[3];
    const float* bt          = (const float*)d_in[4];
    const float* Wg          = (const float*)d_in[5];
    const float* bg          = (const float*)d_in[6];
    const float* promo_tab   = (const float*)d_in[7];
    const float* Ws          = (const float*)d_in[8];
    const float* bs          = (const float*)d_in[9];
    const int*   from_sqs    = (const int*)d_in[10];
    const int*   to_sqs      = (const int*)d_in[11];
    const int*   promo_types = (const int*)d_in[12];
    float*       out         = (float*)d_out;

    // 1) tf32-round + densify A, B
    conv_kernel<<<4224, 256>>>(hidden, Wf, Wt);

    // 2) tensor-core fp/tp GEMM
    const int gemm_smem = 4 * BUFSZ * 4;   // 73728 B
    cudaFuncSetAttribute(gemm_fpt_kernel,
                         cudaFuncAttributeMaxDynamicSharedMemorySize, gemm_smem);
    gemm_fpt_kernel<<<dim3(4, 128), 256, gemm_smem>>>(bf, bt);

    // 3) gp
    gp_kernel<<<64, 256>>>(hidden, Wg, bg);

    // 4) combine
    const int smem_bytes = (32768 + 256 + 256 + 1280) * 4;
    cudaFuncSetAttribute(combine_kernel,
                         cudaFuncAttributeMaxDynamicSharedMemorySize, smem_bytes);
    combine_kernel<<<256, 512, smem_bytes>>>(promo_tab, Ws, bs,
                                             from_sqs, to_sqs, promo_types, out);
}

// round 3
// speedup vs baseline: 2.0176x; 1.1121x over previous
#include <cuda_runtime.h>
#include <cstdint>

// ---------------------------------------------------------------------------
// SpatialPolicyHead: B=256, S=128 (rows 3..66 + row 0), H=1024, D=256, V=1858
//   fp = sq_hidden @ Wf^T + bf          (B*64, 256)
//   tp = sq_hidden @ Wt^T + bt          (B*64, 256)
//   gp = hidden[:,0,:] @ Wg^T + bg      (B, 256)
//   out[b,v] = sum_d relu(fp[b,f(v),d]*tp[b,t(v),d] + gp[b,d] + promo[p(v),d])*Ws[d] + bs
//
// R3: no conv pre-pass (tf32 rna rounding done on fragments in registers,
// A gathered straight from hidden via cp.async). GEMM 128x256 block /
// 64x64 warp tiles (MMA-bound, 1.0 LDS per MMA). Combine: 4 v-slices per
// batch (1024 blocks), gp/Ws register-hoisted.
// ---------------------------------------------------------------------------

// scratch (static device globals -- allocation-free)
__device__ float g_fpt[16384 * 512];     // [B*64][512]: cols 0..255 = fp, 256..511 = tp
__device__ float g_gp [256 * 256];       // [B][256]

// ---------------------------------------------------------------------------
// TF32 tensor-core GEMM.
// grid = (2, 128): blockIdx.x = 0 -> fp (Wf/bf), 1 -> tp (Wt/bt).
// 128(m) x 256(n) x 32(k) block tile, 256 threads = 8 warps (2m x 4n),
// warp tile 64x64. mma.sync.m16n8k8 tf32, cp.async double buffer.
// smem floats: A[2][128][36] + B[2][256][36] = 27648 (110592 B).
// ---------------------------------------------------------------------------
#define KT 32                   // 1024/32 k-tiles
#define ABUF (128 * 36)         // floats per A buffer
#define BBUF (256 * 36)         // floats per B buffer

__device__ __forceinline__ uint32_t tf32u(float x) {
    uint32_t u;
    asm("cvt.rna.tf32.f32 %0, %1;" : "=r"(u) : "f"(x));
    return u;
}

__device__ __forceinline__ void mma_tf32(float* c, const uint32_t* a, const uint32_t* b) {
    asm volatile(
        "mma.sync.aligned.m16n8k8.row.col.f32.tf32.tf32.f32 "
        "{%0,%1,%2,%3}, {%4,%5,%6,%7}, {%8,%9}, {%0,%1,%2,%3};"
        : "+f"(c[0]), "+f"(c[1]), "+f"(c[2]), "+f"(c[3])
        : "r"(a[0]), "r"(a[1]), "r"(a[2]), "r"(a[3]), "r"(b[0]), "r"(b[1]));
}

__global__ void __launch_bounds__(256) gemm_fpt_kernel(
    const float* __restrict__ hidden,
    const float* __restrict__ Wf, const float* __restrict__ Wt,
    const float* __restrict__ bf, const float* __restrict__ bt)
{
    extern __shared__ float smem[];
    float* As = smem;                     // [2][128][36]
    float* Bs = smem + 2 * ABUF;          // [2][256][36]
    const uint32_t sbase = (uint32_t)__cvta_generic_to_shared(smem);
    const uint32_t sA_u  = sbase;
    const uint32_t sB_u  = sbase + 2 * ABUF * 4;

    const int tid  = threadIdx.x;
    const int bn   = blockIdx.x;    // 0 = fp, 1 = tp
    const int bm   = blockIdx.y;    // 0..127
    const int warp = tid >> 5;
    const int lane = tid & 31;
    const int warp_m = warp >> 2;   // 0..1
    const int warp_n = warp & 3;    // 0..3
    const int lr = lane >> 2;       // 0..7
    const int lc = lane & 3;        // 0..3

    // copy mapping: rows crow + 32j, float4 col cc4
    const int crow = tid >> 3;      // 0..31
    const int cc4  = tid & 7;       // 0..7

    // A row gather pointers (4 rows per thread)
    const float* gA[4];
    #pragma unroll
    for (int j = 0; j < 4; j++) {
        const int m = bm * 128 + crow + 32 * j;
        const int hrow = (m >> 6) * 128 + 3 + (m & 63);
        gA[j] = hidden + (size_t)hrow * 1024 + cc4 * 4;
    }
    const float* Wb = bn ? Wt : Wf;
    const float* gB = Wb + (size_t)crow * 1024 + cc4 * 4;

    const uint32_t sAoff = (uint32_t)((crow * 36 + cc4 * 4) * 4);  // bytes
    const uint32_t sBoff = sAoff;

    float acc[4][8][4];
    #pragma unroll
    for (int i = 0; i < 4; i++)
        #pragma unroll
        for (int j = 0; j < 8; j++)
            #pragma unroll
            for (int k = 0; k < 4; k++) acc[i][j][k] = 0.f;

    // prologue: tile 0 -> buffer 0
    #pragma unroll
    for (int j = 0; j < 4; j++)
        asm volatile("cp.async.ca.shared.global [%0], [%1], 16;" ::
            "r"(sA_u + sAoff + j * (32 * 36 * 4)), "l"(gA[j]));
    #pragma unroll
    for (int j = 0; j < 8; j++)
        asm volatile("cp.async.ca.shared.global [%0], [%1], 16;" ::
            "r"(sB_u + sBoff + j * (32 * 36 * 4)), "l"(gB + (size_t)j * 32 * 1024));
    asm volatile("cp.async.commit_group;" ::: "memory");

    int buf = 0;
    for (int t = 0; t < KT; t++) {
        asm volatile("cp.async.wait_group 0;" ::: "memory");
        __syncthreads();

        if (t + 1 < KT) {
            const int nb = buf ^ 1;
            const uint32_t aoff = sA_u + (uint32_t)nb * ABUF * 4 + sAoff;
            const uint32_t boff = sB_u + (uint32_t)nb * BBUF * 4 + sBoff;
            const int kofs = (t + 1) * 32;
            #pragma unroll
            for (int j = 0; j < 4; j++)
                asm volatile("cp.async.ca.shared.global [%0], [%1], 16;" ::
                    "r"(aoff + j * (32 * 36 * 4)), "l"(gA[j] + kofs));
            #pragma unroll
            for (int j = 0; j < 8; j++)
                asm volatile("cp.async.ca.shared.global [%0], [%1], 16;" ::
                    "r"(boff + j * (32 * 36 * 4)), "l"(gB + kofs + (size_t)j * 32 * 1024));
            asm volatile("cp.async.commit_group;" ::: "memory");
        }

        const float* Ab = As + buf * ABUF;
        const float* Bb = Bs + buf * BBUF;
        #pragma unroll
        for (int ks = 0; ks < 4; ks++) {
            uint32_t afr[4][4], bfr[8][2];
            #pragma unroll
            for (int mt = 0; mt < 4; mt++) {
                const float* p = Ab + (warp_m * 64 + mt * 16 + lr) * 36 + ks * 8 + lc;
                afr[mt][0] = tf32u(p[0]);
                afr[mt][1] = tf32u(p[8 * 36]);
                afr[mt][2] = tf32u(p[4]);
                afr[mt][3] = tf32u(p[8 * 36 + 4]);
            }
            #pragma unroll
            for (int nt = 0; nt < 8; nt++) {
                const float* q = Bb + (warp_n * 64 + nt * 8 + lr) * 36 + ks * 8 + lc;
                bfr[nt][0] = tf32u(q[0]);
                bfr[nt][1] = tf32u(q[4]);
            }
            #pragma unroll
            for (int mt = 0; mt < 4; mt++)
                #pragma unroll
                for (int nt = 0; nt < 8; nt++)
                    mma_tf32(acc[mt][nt], afr[mt], bfr[nt]);
        }
        buf ^= 1;
    }

    // epilogue: add bias, store to g_fpt (fp at cols 0..255, tp at 256..511)
    const float* bia_base = bn ? bt : bf;
    const int ncol_base = bn * 256;
    #pragma unroll
    for (int mt = 0; mt < 4; mt++) {
        const int gm0 = bm * 128 + warp_m * 64 + mt * 16 + lr;
        #pragma unroll
        for (int nt = 0; nt < 8; nt++) {
            const int n_loc = warp_n * 64 + nt * 8 + (lc << 1);   // 0..255
            const float b0 = bia_base[n_loc], b1 = bia_base[n_loc + 1];
            float2 r0, r1;
            r0.x = acc[mt][nt][0] + b0; r0.y = acc[mt][nt][1] + b1;
            r1.x = acc[mt][nt][2] + b0; r1.y = acc[mt][nt][3] + b1;
            *(float2*)&g_fpt[(size_t)gm0 * 512 + ncol_base + n_loc]       = r0;
            *(float2*)&g_fpt[(size_t)(gm0 + 8) * 512 + ncol_base + n_loc] = r1;
        }
    }
}

// ---------------------------------------------------------------------------
// gp GEMM (fp32, tiny): 64 blocks x 4 batches.
// ---------------------------------------------------------------------------
__global__ void __launch_bounds__(256) gp_kernel(
    const float* __restrict__ hidden,
    const float* __restrict__ Wg, const float* __restrict__ bg)
{
    __shared__ float sh[4][1024];
    const int tid = threadIdx.x;
    const int b0  = blockIdx.x * 4;

    #pragma unroll
    for (int i = 0; i < 4; i++) {
        const int idx = tid + i * 256;
        const int row = idx >> 8;
        const int col = idx & 255;
        ((float4*)&sh[row][0])[col] =
            ((const float4*)(hidden + (size_t)(b0 + row) * 131072))[col];
    }
    __syncthreads();

    const int n = tid;
    const float4* w4 = (const float4*)(Wg + (size_t)n * 1024);
    float acc0 = 0.f, acc1 = 0.f, acc2 = 0.f, acc3 = 0.f;
    #pragma unroll 4
    for (int k4 = 0; k4 < 256; k4++) {
        const float4 w  = w4[k4];
        const float4 h0 = ((const float4*)&sh[0][0])[k4];
        const float4 h1 = ((const float4*)&sh[1][0])[k4];
        const float4 h2 = ((const float4*)&sh[2][0])[k4];
        const float4 h3 = ((const float4*)&sh[3][0])[k4];
        acc0 = fmaf(w.x, h0.x, acc0); acc0 = fmaf(w.y, h0.y, acc0);
        acc0 = fmaf(w.z, h0.z, acc0); acc0 = fmaf(w.w, h0.w, acc0);
        acc1 = fmaf(w.x, h1.x, acc1); acc1 = fmaf(w.y, h1.y, acc1);
        acc1 = fmaf(w.z, h1.z, acc1); acc1 = fmaf(w.w, h1.w, acc1);
        acc2 = fmaf(w.x, h2.x, acc2); acc2 = fmaf(w.y, h2.y, acc2);
        acc2 = fmaf(w.z, h2.z, acc2); acc2 = fmaf(w.w, h2.w, acc2);
        acc3 = fmaf(w.x, h3.x, acc3); acc3 = fmaf(w.y, h3.y, acc3);
        acc3 = fmaf(w.z, h3.z, acc3); acc3 = fmaf(w.w, h3.w, acc3);
    }
    const float bias = bg[n];
    g_gp[(size_t)(b0 + 0) * 256 + n] = acc0 + bias;
    g_gp[(size_t)(b0 + 1) * 256 + n] = acc1 + bias;
    g_gp[(size_t)(b0 + 2) * 256 + n] = acc2 + bias;
    g_gp[(size_t)(b0 + 3) * 256 + n] = acc3 + bias;
}

// ---------------------------------------------------------------------------
// Combine: 1024 blocks = 4 v-slices x 256 batches, 512 threads.
// smem = fp/tp (64x512) + promo (5x256) = 136192 B. gp/Ws hoisted to regs.
// One warp per v; 6 x LDS.128 per v; shfl reduce.
// ---------------------------------------------------------------------------
#define VSLICE 465   // ceil(1858/4)

__global__ void __launch_bounds__(512) combine_kernel(
    const float* __restrict__ promo_tab, const float* __restrict__ Ws,
    const float* __restrict__ bs,
    const int* __restrict__ from_sqs, const int* __restrict__ to_sqs,
    const int* __restrict__ promo_types,
    float* __restrict__ out)
{
    extern __shared__ float smem[];
    float* fpt_s   = smem;             // 64*512
    float* promo_s = smem + 32768;     // 5*256

    const int tid   = threadIdx.x;
    const int b     = blockIdx.x >> 2;
    const int slice = blockIdx.x & 3;

    // stage fp/tp: 8192 float4 / 512 threads
    const float4* src = (const float4*)(g_fpt + (size_t)b * 32768);
    float4* dst = (float4*)fpt_s;
    #pragma unroll
    for (int i = 0; i < 16; i++)
        dst[tid + i * 512] = src[tid + i * 512];
    if (tid < 320)
        ((float4*)promo_s)[tid] = ((const float4*)promo_tab)[tid];

    const int lane = tid & 31;
    const int warp = tid >> 5;

    // register-hoisted gp row and Ws (8 d-slots per lane: lane*4 and 128+lane*4)
    const float4 gpa = *(const float4*)(g_gp + (size_t)b * 256 + lane * 4);
    const float4 gpb = *(const float4*)(g_gp + (size_t)b * 256 + 128 + lane * 4);
    const float4 wsa = *(const float4*)(Ws + lane * 4);
    const float4 wsb = *(const float4*)(Ws + 128 + lane * 4);
    const float bs0 = __ldg(bs);

    __syncthreads();

    const int vstart = slice * VSLICE;
    const int vend   = min(1858, vstart + VSLICE);

    for (int v = vstart + warp; v < vend; v += 16) {
        const int f = __ldg(from_sqs + v);
        const int t = __ldg(to_sqs + v);
        const int p = __ldg(promo_types + v);
        const float* fr = fpt_s + f * 512;
        const float* tr = fpt_s + t * 512 + 256;
        const float* pr = promo_s + p * 256;

        const float4 a0 = *(const float4*)(fr + lane * 4);
        const float4 a1 = *(const float4*)(fr + 128 + lane * 4);
        const float4 t0 = *(const float4*)(tr + lane * 4);
        const float4 t1 = *(const float4*)(tr + 128 + lane * 4);
        const float4 p0 = *(const float4*)(pr + lane * 4);
        const float4 p1 = *(const float4*)(pr + 128 + lane * 4);

        float acc;
        {
            const float c0 = fmaf(a0.x, t0.x, gpa.x) + p0.x;
            const float c1 = fmaf(a0.y, t0.y, gpa.y) + p0.y;
            const float c2 = fmaf(a0.z, t0.z, gpa.z) + p0.z;
            const float c3 = fmaf(a0.w, t0.w, gpa.w) + p0.w;
            const float d0 = fmaf(a1.x, t1.x, gpb.x) + p1.x;
            const float d1 = fmaf(a1.y, t1.y, gpb.y) + p1.y;
            const float d2 = fmaf(a1.z, t1.z, gpb.z) + p1.z;
            const float d3 = fmaf(a1.w, t1.w, gpb.w) + p1.w;
            acc  = fmaxf(c0, 0.f) * wsa.x;
            acc  = fmaf(fmaxf(c1, 0.f), wsa.y, acc);
            acc  = fmaf(fmaxf(c2, 0.f), wsa.z, acc);
            acc  = fmaf(fmaxf(c3, 0.f), wsa.w, acc);
            acc  = fmaf(fmaxf(d0, 0.f), wsb.x, acc);
            acc  = fmaf(fmaxf(d1, 0.f), wsb.y, acc);
            acc  = fmaf(fmaxf(d2, 0.f), wsb.z, acc);
            acc  = fmaf(fmaxf(d3, 0.f), wsb.w, acc);
        }
        #pragma unroll
        for (int off = 16; off > 0; off >>= 1)
            acc += __shfl_xor_sync(0xffffffffu, acc, off);
        if (lane == 0)
            out[(size_t)b * 1858 + v] = acc + bs0;
    }
}

// ---------------------------------------------------------------------------
extern "C" void kernel_launch(void* const* d_in, const int* in_sizes, int n_in,
                              void* d_out, int out_size)
{
    (void)in_sizes; (void)n_in; (void)out_size;

    const float* hidden      = (const float*)d_in[0];
    const float* Wf          = (const float*)d_in[1];
    const float* bf          = (const float*)d_in[2];
    const float* Wt          = (const float*)d_in[3];
    const float* bt          = (const float*)d_in[4];
    const float* Wg          = (const float*)d_in[5];
    const float* bg          = (const float*)d_in[6];
    const float* promo_tab   = (const float*)d_in[7];
    const float* Ws          = (const float*)d_in[8];
    const float* bs          = (const float*)d_in[9];
    const int*   from_sqs    = (const int*)d_in[10];
    const int*   to_sqs      = (const int*)d_in[11];
    const int*   promo_types = (const int*)d_in[12];
    float*       out         = (float*)d_out;

    // 1) tensor-core fp/tp GEMM (gathers + tf32-rounds in-flight)
    const int gemm_smem = (2 * ABUF + 2 * BBUF) * 4;   // 110592 B
    cudaFuncSetAttribute(gemm_fpt_kernel,
                         cudaFuncAttributeMaxDynamicSharedMemorySize, gemm_smem);
    gemm_fpt_kernel<<<dim3(2, 128), 256, gemm_smem>>>(hidden, Wf, Wt, bf, bt);

    // 2) gp
    gp_kernel<<<64, 256>>>(hidden, Wg, bg);

    // 3) combine: 4 v-slices per batch
    const int comb_smem = (32768 + 1280) * 4;          // 136192 B
    cudaFuncSetAttribute(combine_kernel,
                         cudaFuncAttributeMaxDynamicSharedMemorySize, comb_smem);
    combine_kernel<<<1024, 512, comb_smem>>>(promo_tab, Ws, bs,
                                             from_sqs, to_sqs, promo_types, out);
}

// round 5
// speedup vs baseline: 2.3568x; 1.1681x over previous
#include <cuda_runtime.h>
#include <cuda_fp16.h>
#include <cstdint>

// ---------------------------------------------------------------------------
// SpatialPolicyHead: B=256, S=128 (rows 3..66 + row 0), H=1024, D=256, V=1858
//   fp = sq_hidden @ Wf^T + bf          (B*64, 256)
//   tp = sq_hidden @ Wt^T + bt          (B*64, 256)
//   gp = hidden[:,0,:] @ Wg^T + bg      (B, 256)
//   out[b,v] = sum_d relu(fp[b,f(v),d]*tp[b,t(v),d] + gp[b,d] + promo[p(v),d])*Ws[d] + bs
//
// R5: fp16 mma.sync.m16n8k16 (same 10-bit mantissa as tf32, 2x rate).
// fp16 pre-pass (gather+convert). Combine: 256 blocks x 1024 threads.
// ---------------------------------------------------------------------------

// scratch (static device globals -- allocation-free)
__device__ __half g_Ah[16384 * 1024];   // gathered sq_hidden rows, fp16
__device__ __half g_Bh[512 * 1024];     // Wf (0..255) ++ Wt (256..511), fp16
__device__ float  g_fpt[16384 * 512];   // [B*64][512]: cols 0..255 fp, 256..511 tp
__device__ float  g_gp [256 * 256];     // [B][256]

// ---------------------------------------------------------------------------
// Pre-pass: gather + fp16-convert A; convert B.
// Blocks [0,4096): A; [4096,4224): B. Each thread: 4 float4 -> 4x(2 half2).
// ---------------------------------------------------------------------------
__global__ void __launch_bounds__(256) conv_kernel(
    const float* __restrict__ hidden,
    const float* __restrict__ Wf, const float* __restrict__ Wt)
{
    const int tid = threadIdx.x;
    if (blockIdx.x < 4096) {
        const size_t base = (size_t)blockIdx.x * 1024;
        #pragma unroll
        for (int j = 0; j < 4; j++) {
            const size_t i = base + tid + j * 256;   // float4 index
            const int m  = (int)(i >> 8);
            const int c4 = (int)(i & 255);
            const int row = (m >> 6) * 128 + 3 + (m & 63);
            const float4 v = ((const float4*)(hidden + (size_t)row * 1024))[c4];
            __half2 h0 = __floats2half2_rn(v.x, v.y);
            __half2 h1 = __floats2half2_rn(v.z, v.w);
            ((__half2*)g_Ah)[2 * i]     = h0;
            ((__half2*)g_Ah)[2 * i + 1] = h1;
        }
    } else {
        const size_t base = (size_t)(blockIdx.x - 4096) * 1024;
        #pragma unroll
        for (int j = 0; j < 4; j++) {
            const size_t i = base + tid + j * 256;
            const int n  = (int)(i >> 8);
            const int c4 = (int)(i & 255);
            const float* src = (n < 256) ? (Wf + (size_t)n * 1024)
                                         : (Wt + (size_t)(n - 256) * 1024);
            const float4 v = ((const float4*)src)[c4];
            __half2 h0 = __floats2half2_rn(v.x, v.y);
            __half2 h1 = __floats2half2_rn(v.z, v.w);
            ((__half2*)g_Bh)[2 * i]     = h0;
            ((__half2*)g_Bh)[2 * i + 1] = h1;
        }
    }
}

// ---------------------------------------------------------------------------
// fp16 tensor-core GEMM: grid (2,128): x=0 -> fp (Wf/bf), 1 -> tp (Wt/bt).
// 128(m) x 256(n) x 32(k) block tile, 256 threads = 8 warps (2m x 4n),
// warp tile 64x64. mma.sync.m16n8k16 f16->f32, cp.async double buffer.
// smem halves: A[2][128][40] + B[2][256][40] -> 61440 bytes dynamic.
// ---------------------------------------------------------------------------
#define KT 32                    // 1024/32 k-tiles
#define AST 40                   // halves per smem row (80 B, conflict-free)
#define ABUFH (128 * AST)        // halves per A buffer
#define BBUFH (256 * AST)        // halves per B buffer
#define GEMM_SMEM ((2 * ABUFH + 2 * BBUFH) * 2)   // 61440 B

__device__ __forceinline__ void mma_f16(float* c, const uint32_t* a, const uint32_t* b) {
    asm volatile(
        "mma.sync.aligned.m16n8k16.row.col.f32.f16.f16.f32 "
        "{%0,%1,%2,%3}, {%4,%5,%6,%7}, {%8,%9}, {%0,%1,%2,%3};"
        : "+f"(c[0]), "+f"(c[1]), "+f"(c[2]), "+f"(c[3])
        : "r"(a[0]), "r"(a[1]), "r"(a[2]), "r"(a[3]), "r"(b[0]), "r"(b[1]));
}

__global__ void __launch_bounds__(256) gemm_fpt_kernel(
    const float* __restrict__ bf, const float* __restrict__ bt)
{
    extern __shared__ __half hsm[];
    __half* As = hsm;                  // [2][128][AST]
    __half* Bs = hsm + 2 * ABUFH;      // [2][256][AST]
    uint32_t sbase;
    asm("{ .reg .u64 t; cvta.to.shared.u64 t, %1; cvt.u32.u64 %0, t; }"
        : "=r"(sbase) : "l"(hsm));
    const uint32_t sA_u = sbase;
    const uint32_t sB_u = sbase + 2 * ABUFH * 2;

    const int tid  = threadIdx.x;
    const int bn   = blockIdx.x;    // 0 = fp, 1 = tp
    const int bm   = blockIdx.y;    // 0..127
    const int warp = tid >> 5;
    const int lane = tid & 31;
    const int warp_m = warp >> 2;   // 0..1
    const int warp_n = warp & 3;    // 0..3
    const int lr = lane >> 2;       // 0..7
    const int lc = lane & 3;        // 0..3

    // A copy: row = tid>>1, two 16B chunks cc = (tid&1)*2, +1
    const int a_row = tid >> 1;
    const int a_cc  = (tid & 1) * 2;
    const __half* gA = g_Ah + (size_t)(bm * 128 + a_row) * 1024 + a_cc * 8;
    const uint32_t sAoff = (uint32_t)(a_row * (AST * 2) + a_cc * 16);

    // B copy: 4 chunks: id = tid + 256j -> row = id>>2, cc = id&3
    const __half* gBbase = g_Bh + (size_t)bn * 256 * 1024;

    float acc[4][8][4];
    #pragma unroll
    for (int i = 0; i < 4; i++)
        #pragma unroll
        for (int j = 0; j < 8; j++)
            #pragma unroll
            for (int k = 0; k < 4; k++) acc[i][j][k] = 0.f;

    auto load_tile = [&](int t, int buf) {
        const uint32_t aB = sA_u + (uint32_t)buf * ABUFH * 2;
        const uint32_t bB = sB_u + (uint32_t)buf * BBUFH * 2;
        asm volatile("cp.async.ca.shared.global [%0], [%1], 16;" ::
            "r"(aB + sAoff), "l"(gA + t * 32));
        asm volatile("cp.async.ca.shared.global [%0], [%1], 16;" ::
            "r"(aB + sAoff + 16), "l"(gA + t * 32 + 8));
        #pragma unroll
        for (int j = 0; j < 4; j++) {
            const int id  = tid + 256 * j;
            const int row = id >> 2;
            const int cc  = id & 3;
            asm volatile("cp.async.ca.shared.global [%0], [%1], 16;" ::
                "r"(bB + (uint32_t)(row * (AST * 2) + cc * 16)),
                "l"(gBbase + (size_t)row * 1024 + t * 32 + cc * 8));
        }
        asm volatile("cp.async.commit_group;" ::: "memory");
    };

    // prologue: tile 0 -> buffer 0
    load_tile(0, 0);

    int buf = 0;
    for (int t = 0; t < KT; t++) {
        asm volatile("cp.async.wait_group 0;" ::: "memory");
        __syncthreads();

        if (t + 1 < KT)
            load_tile(t + 1, buf ^ 1);

        const __half* Ab = As + buf * ABUFH;
        const __half* Bb = Bs + buf * BBUFH;
        #pragma unroll
        for (int ks = 0; ks < 2; ks++) {
            uint32_t afr[4][4], bfr[8][2];
            #pragma unroll
            for (int mt = 0; mt < 4; mt++) {
                const __half* p = Ab + (warp_m * 64 + mt * 16 + lr) * AST + ks * 16 + 2 * lc;
                afr[mt][0] = *(const uint32_t*)(p);
                afr[mt][1] = *(const uint32_t*)(p + 8 * AST);
                afr[mt][2] = *(const uint32_t*)(p + 8);
                afr[mt][3] = *(const uint32_t*)(p + 8 * AST + 8);
            }
            #pragma unroll
            for (int nt = 0; nt < 8; nt++) {
                const __half* q = Bb + (warp_n * 64 + nt * 8 + lr) * AST + ks * 16 + 2 * lc;
                bfr[nt][0] = *(const uint32_t*)(q);
                bfr[nt][1] = *(const uint32_t*)(q + 8);
            }
            #pragma unroll
            for (int mt = 0; mt < 4; mt++)
                #pragma unroll
                for (int nt = 0; nt < 8; nt++)
                    mma_f16(acc[mt][nt], afr[mt], bfr[nt]);
        }
        buf ^= 1;
    }

    // epilogue: add bias, store to g_fpt (fp at cols 0..255, tp at 256..511)
    const float* bia_base = bn ? bt : bf;
    const int ncol_base = bn * 256;
    #pragma unroll
    for (int mt = 0; mt < 4; mt++) {
        const int gm0 = bm * 128 + warp_m * 64 + mt * 16 + lr;
        #pragma unroll
        for (int nt = 0; nt < 8; nt++) {
            const int n_loc = warp_n * 64 + nt * 8 + (lc << 1);   // 0..255
            const float b0 = bia_base[n_loc], b1 = bia_base[n_loc + 1];
            float2 r0, r1;
            r0.x = acc[mt][nt][0] + b0; r0.y = acc[mt][nt][1] + b1;
            r1.x = acc[mt][nt][2] + b0; r1.y = acc[mt][nt][3] + b1;
            *(float2*)&g_fpt[(size_t)gm0 * 512 + ncol_base + n_loc]       = r0;
            *(float2*)&g_fpt[(size_t)(gm0 + 8) * 512 + ncol_base + n_loc] = r1;
        }
    }
}

// ---------------------------------------------------------------------------
// gp GEMM (fp32, tiny): 64 blocks x 4 batches.
// ---------------------------------------------------------------------------
__global__ void __launch_bounds__(256) gp_kernel(
    const float* __restrict__ hidden,
    const float* __restrict__ Wg, const float* __restrict__ bg)
{
    __shared__ float sh[4][1024];
    const int tid = threadIdx.x;
    const int b0  = blockIdx.x * 4;

    #pragma unroll
    for (int i = 0; i < 4; i++) {
        const int idx = tid + i * 256;
        const int row = idx >> 8;
        const int col = idx & 255;
        ((float4*)&sh[row][0])[col] =
            ((const float4*)(hidden + (size_t)(b0 + row) * 131072))[col];
    }
    __syncthreads();

    const int n = tid;
    const float4* w4 = (const float4*)(Wg + (size_t)n * 1024);
    float acc0 = 0.f, acc1 = 0.f, acc2 = 0.f, acc3 = 0.f;
    #pragma unroll 4
    for (int k4 = 0; k4 < 256; k4++) {
        const float4 w  = w4[k4];
        const float4 h0 = ((const float4*)&sh[0][0])[k4];
        const float4 h1 = ((const float4*)&sh[1][0])[k4];
        const float4 h2 = ((const float4*)&sh[2][0])[k4];
        const float4 h3 = ((const float4*)&sh[3][0])[k4];
        acc0 = fmaf(w.x, h0.x, acc0); acc0 = fmaf(w.y, h0.y, acc0);
        acc0 = fmaf(w.z, h0.z, acc0); acc0 = fmaf(w.w, h0.w, acc0);
        acc1 = fmaf(w.x, h1.x, acc1); acc1 = fmaf(w.y, h1.y, acc1);
        acc1 = fmaf(w.z, h1.z, acc1); acc1 = fmaf(w.w, h1.w, acc1);
        acc2 = fmaf(w.x, h2.x, acc2); acc2 = fmaf(w.y, h2.y, acc2);
        acc2 = fmaf(w.z, h2.z, acc2); acc2 = fmaf(w.w, h2.w, acc2);
        acc3 = fmaf(w.x, h3.x, acc3); acc3 = fmaf(w.y, h3.y, acc3);
        acc3 = fmaf(w.z, h3.z, acc3); acc3 = fmaf(w.w, h3.w, acc3);
    }
    const float bias = bg[n];
    g_gp[(size_t)(b0 + 0) * 256 + n] = acc0 + bias;
    g_gp[(size_t)(b0 + 1) * 256 + n] = acc1 + bias;
    g_gp[(size_t)(b0 + 2) * 256 + n] = acc2 + bias;
    g_gp[(size_t)(b0 + 3) * 256 + n] = acc3 + bias;
}

// ---------------------------------------------------------------------------
// Combine: 256 blocks (one per batch), 1024 threads (32 warps).
// smem = fp/tp (64x512) + promo (5x256) = 136192 B. gp/Ws reg-hoisted.
// One warp per v; 6 x LDS.128 per v; shfl reduce.
// ---------------------------------------------------------------------------
__global__ void __launch_bounds__(1024) combine_kernel(
    const float* __restrict__ promo_tab, const float* __restrict__ Ws,
    const float* __restrict__ bs,
    const int* __restrict__ from_sqs, const int* __restrict__ to_sqs,
    const int* __restrict__ promo_types,
    float* __restrict__ out)
{
    extern __shared__ float smem[];
    float* fpt_s   = smem;             // 64*512
    float* promo_s = smem + 32768;     // 5*256

    const int tid = threadIdx.x;
    const int b   = blockIdx.x;

    // stage fp/tp: 8192 float4 / 1024 threads
    const float4* src = (const float4*)(g_fpt + (size_t)b * 32768);
    float4* dst = (float4*)fpt_s;
    #pragma unroll
    for (int i = 0; i < 8; i++)
        dst[tid + i * 1024] = src[tid + i * 1024];
    if (tid < 320)
        ((float4*)promo_s)[tid] = ((const float4*)promo_tab)[tid];

    const int lane = tid & 31;
    const int warp = tid >> 5;

    // register-hoisted gp row and Ws (8 d-slots per lane)
    const float4 gpa = *(const float4*)(g_gp + (size_t)b * 256 + lane * 4);
    const float4 gpb = *(const float4*)(g_gp + (size_t)b * 256 + 128 + lane * 4);
    const float4 wsa = *(const float4*)(Ws + lane * 4);
    const float4 wsb = *(const float4*)(Ws + 128 + lane * 4);
    const float bs0 = __ldg(bs);

    __syncthreads();

    for (int v = warp; v < 1858; v += 32) {
        const int f = __ldg(from_sqs + v);
        const int t = __ldg(to_sqs + v);
        const int p = __ldg(promo_types + v);
        const float* fr = fpt_s + f * 512;
        const float* tr = fpt_s + t * 512 + 256;
        const float* pr = promo_s + p * 256;

        const float4 a0 = *(const float4*)(fr + lane * 4);
        const float4 a1 = *(const float4*)(fr + 128 + lane * 4);
        const float4 t0 = *(const float4*)(tr + lane * 4);
        const float4 t1 = *(const float4*)(tr + 128 + lane * 4);
        const float4 p0 = *(const float4*)(pr + lane * 4);
        const float4 p1 = *(const float4*)(pr + 128 + lane * 4);

        float acc;
        {
            const float c0 = fmaf(a0.x, t0.x, gpa.x) + p0.x;
            const float c1 = fmaf(a0.y, t0.y, gpa.y) + p0.y;
            const float c2 = fmaf(a0.z, t0.z, gpa.z) + p0.z;
            const float c3 = fmaf(a0.w, t0.w, gpa.w) + p0.w;
            const float d0 = fmaf(a1.x, t1.x, gpb.x) + p1.x;
            const float d1 = fmaf(a1.y, t1.y, gpb.y) + p1.y;
            const float d2 = fmaf(a1.z, t1.z, gpb.z) + p1.z;
            const float d3 = fmaf(a1.w, t1.w, gpb.w) + p1.w;
            acc  = fmaxf(c0, 0.f) * wsa.x;
            acc  = fmaf(fmaxf(c1, 0.f), wsa.y, acc);
            acc  = fmaf(fmaxf(c2, 0.f), wsa.z, acc);
            acc  = fmaf(fmaxf(c3, 0.f), wsa.w, acc);
            acc  = fmaf(fmaxf(d0, 0.f), wsb.x, acc);
            acc  = fmaf(fmaxf(d1, 0.f), wsb.y, acc);
            acc  = fmaf(fmaxf(d2, 0.f), wsb.z, acc);
            acc  = fmaf(fmaxf(d3, 0.f), wsb.w, acc);
        }
        #pragma unroll
        for (int off = 16; off > 0; off >>= 1)
            acc += __shfl_xor_sync(0xffffffffu, acc, off);
        if (lane == 0)
            out[(size_t)b * 1858 + v] = acc + bs0;
    }
}

// ---------------------------------------------------------------------------
extern "C" void kernel_launch(void* const* d_in, const int* in_sizes, int n_in,
                              void* d_out, int out_size)
{
    (void)in_sizes; (void)n_in; (void)out_size;

    const float* hidden      = (const float*)d_in[0];
    const float* Wf          = (const float*)d_in[1];
    const float* bf          = (const float*)d_in[2];
    const float* Wt          = (const float*)d_in[3];
    const float* bt          = (const float*)d_in[4];
    const float* Wg          = (const float*)d_in[5];
    const float* bg          = (const float*)d_in[6];
    const float* promo_tab   = (const float*)d_in[7];
    const float* Ws          = (const float*)d_in[8];
    const float* bs          = (const float*)d_in[9];
    const int*   from_sqs    = (const int*)d_in[10];
    const int*   to_sqs      = (const int*)d_in[11];
    const int*   promo_types = (const int*)d_in[12];
    float*       out         = (float*)d_out;

    // 1) gather + fp16 convert pre-pass
    conv_kernel<<<4224, 256>>>(hidden, Wf, Wt);

    // 2) fp16 tensor-core fp/tp GEMM
    cudaFuncSetAttribute(gemm_fpt_kernel,
                         cudaFuncAttributeMaxDynamicSharedMemorySize, GEMM_SMEM);
    gemm_fpt_kernel<<<dim3(2, 128), 256, GEMM_SMEM>>>(bf, bt);

    // 3) gp
    gp_kernel<<<64, 256>>>(hidden, Wg, bg);

    // 4) combine
    const int comb_smem = (32768 + 1280) * 4;
    cudaFuncSetAttribute(combine_kernel,
                         cudaFuncAttributeMaxDynamicSharedMemorySize, comb_smem);
    combine_kernel<<<256, 1024, comb_smem>>>(promo_tab, Ws, bs,
                                             from_sqs, to_sqs, promo_types, out);
}